// round 9
// baseline (speedup 1.0000x reference)
#include <cuda_runtime.h>
#include <math.h>

// D_MODEL=300, L=512, B=512, OUT=4.
// diag[e,i] = fmap[i,i,e] = sum_l e2[i,l,i] * e1[i,l,e], i in [0,300)
// Split:  diag[e,i] = scale * sum_l s[i,l]*emb1[x1[i,l]][e]      (term1, gather)
//                   +          sum_l s[i,l]*pe[l][e]             (term2, dense GEMM)
// with    s[i,l] = emb2[x2[i,l]][i]*scale + pe[l][i]

#define D     300
#define LSEQ  512
#define OUTC  4
#define NCH   4     // term1 l-split
#define CHUNK 128   // LSEQ / NCH
#define DKZ   4     // combine K-split (128 per block)
#define HKZ   5     // fc1 K-split
#define KT1   60    // fc1 K per block (5*60=300)
#define RT    16    // reduce tile

__device__ float g_pe[LSEQ * D];          // [l][d]
__device__ float g_s[D * LSEQ];           // [i][l]
__device__ float g_part[NCH * D * D];     // [chunk][i][e]  (term1 partials)
__device__ float g_dpart[DKZ * D * D];    // term2 partials [kz][e][i]
__device__ float g_diag[D * D];           // reduced diag   [e][i]
__device__ float g_hpart[HKZ * D * D];    // fc1 partials   [kz][e][j]

// ---------------------------------------------------------------------------
// Kernel 0: positional encoding, float32 (matches jnp float32 path).
// ---------------------------------------------------------------------------
__global__ void pe_kernel() {
    int idx = blockIdx.x * blockDim.x + threadIdx.x;
    if (idx >= LSEQ * D) return;
    int l = idx / D;
    int d = idx % D;
    int k = d >> 1;
    const float coef = -9.210340371976184f / (float)D;   // -ln(10000)/300
    float divv = expf((float)(2 * k) * coef);
    float ang  = (float)l * divv;
    g_pe[idx] = (d & 1) ? cosf(ang) : sinf(ang);
}

// ---------------------------------------------------------------------------
// Kernel 1: term1 partials. One block per (i, l-chunk of 128). grid (4,300).
// ---------------------------------------------------------------------------
__global__ __launch_bounds__(320) void term1_kernel(
    const int*   __restrict__ x1,
    const int*   __restrict__ x2,
    const float* __restrict__ emb1,
    const float* __restrict__ emb2)
{
    const int chunk = blockIdx.x;          // 0..3
    const int i     = blockIdx.y;          // 0..299
    const int tid   = threadIdx.x;
    const float scale = 17.320508075688775f;  // sqrt(300)

    __shared__ float s_sh[CHUNK];
    __shared__ int   r1_sh[CHUNK];

    if (tid < CHUNK) {
        int l  = chunk * CHUNK + tid;
        int t2 = x2[i * LSEQ + l];
        float sv = fmaf(emb2[t2 * D + i], scale, g_pe[l * D + i]);
        s_sh[tid] = sv;
        g_s[i * LSEQ + l] = sv;
        r1_sh[tid] = x1[i * LSEQ + l] * D;
    }
    __syncthreads();

    if (tid < D) {
        const int e = tid;
        float acc[8];
        #pragma unroll
        for (int u = 0; u < 8; ++u) acc[u] = 0.f;
        #pragma unroll 2
        for (int l = 0; l < CHUNK; l += 8) {
            #pragma unroll
            for (int u = 0; u < 8; ++u)
                acc[u] = fmaf(s_sh[l + u], emb1[r1_sh[l + u] + e], acc[u]);
        }
        float r = ((acc[0] + acc[1]) + (acc[2] + acc[3]))
                + ((acc[4] + acc[5]) + (acc[6] + acc[7]));
        g_part[(chunk * D + i) * D + e] = r;
    }
}

// ---------------------------------------------------------------------------
// Kernel 2: term2 GEMM partials.
//   g_dpart[kz][e][i] = sum_{l in 128-window kz} s[i,l]*pe[l][e]
// grid (10,10,4), 128 threads (16,8). Thread tile 4e x 2i (tx -> i:
// coalesced float2 stores). k-major smem tiles for vector LDS:
// 1 LDS.64 + 1 LDS.128 + 8 FMA per k.
// ---------------------------------------------------------------------------
__global__ __launch_bounds__(128) void combine_kernel()
{
    __shared__ float sh_st[128][34];   // [k][i_local], pad 34 (8B-aligned rows)
    __shared__ float sh_pe[128][36];   // [k][e_local], pad 36 (16B-aligned rows)

    const int tx  = threadIdx.x;       // 0..15 -> i = i0 + 2*tx + {0,1}
    const int ty  = threadIdx.y;       // 0..7  -> e = e0 + 4*ty + {0..3}
    const int lin = ty * 16 + tx;
    const int e0  = blockIdx.x * 32;
    const int i0  = blockIdx.y * 32;
    const int kz  = blockIdx.z;        // 0..3
    const int kb  = kz * 128;

    float acc0[4] = {0.f, 0.f, 0.f, 0.f};   // i = i0+2tx
    float acc1[4] = {0.f, 0.f, 0.f, 0.f};   // i = i0+2tx+1

    // stage s tile transposed: 32 i-rows x 128 k (float4 reads, scalar stores)
    #pragma unroll
    for (int t = 0; t < 8; ++t) {
        int idx = lin + t * 128;           // 0..1023
        int row = idx >> 5;                // 0..31 (i_local)
        int kk  = (idx & 31) * 4;          // 0..124
        float4 v = make_float4(0.f, 0.f, 0.f, 0.f);
        int ii = i0 + row;
        if (ii < D)
            v = *reinterpret_cast<const float4*>(g_s + ii * LSEQ + kb + kk);
        sh_st[kk][row] = v.x; sh_st[kk + 1][row] = v.y;
        sh_st[kk + 2][row] = v.z; sh_st[kk + 3][row] = v.w;
    }
    // stage pe tile (naturally k-major): 128 k-rows x 32 e (float4)
    #pragma unroll
    for (int t = 0; t < 8; ++t) {
        int idx = lin + t * 128;           // 0..1023
        int row = idx >> 3;                // 0..127 (k_local)
        int cc  = (idx & 7) * 4;           // 0..28
        int e   = e0 + cc;
        float4 v = make_float4(0.f, 0.f, 0.f, 0.f);
        if (e <= D - 4)
            v = *reinterpret_cast<const float4*>(g_pe + (kb + row) * D + e);
        *reinterpret_cast<float4*>(&sh_pe[row][cc]) = v;
    }
    __syncthreads();

    #pragma unroll 4
    for (int k = 0; k < 128; ++k) {
        float2 sv = *reinterpret_cast<const float2*>(&sh_st[k][2 * tx]);
        float4 pv = *reinterpret_cast<const float4*>(&sh_pe[k][4 * ty]);
        acc0[0] = fmaf(sv.x, pv.x, acc0[0]);
        acc0[1] = fmaf(sv.x, pv.y, acc0[1]);
        acc0[2] = fmaf(sv.x, pv.z, acc0[2]);
        acc0[3] = fmaf(sv.x, pv.w, acc0[3]);
        acc1[0] = fmaf(sv.y, pv.x, acc1[0]);
        acc1[1] = fmaf(sv.y, pv.y, acc1[1]);
        acc1[2] = fmaf(sv.y, pv.z, acc1[2]);
        acc1[3] = fmaf(sv.y, pv.w, acc1[3]);
    }

    const int ip = i0 + 2 * tx;             // even pair (ip, ip+1)
    if (ip < D) {                            // D even -> pair fully valid
        #pragma unroll
        for (int u = 0; u < 4; ++u) {
            int e = e0 + 4 * ty + u;
            if (e < D) {
                float2 v = make_float2(acc0[u], acc1[u]);
                *reinterpret_cast<float2*>(g_dpart + kz * D * D + e * D + ip) = v;
            }
        }
    }
}

// ---------------------------------------------------------------------------
// Kernel 2b: reduce partials into g_diag. 16x16 tiles, grid (19,19) = 361
// blocks, 256 threads, one output per thread.
//   g_diag[e][i] = scale * sum_c g_part[c][i][e]  (transposed via smem)
//                +         sum_z g_dpart[z][e][i]
// ---------------------------------------------------------------------------
__global__ __launch_bounds__(256) void reduce_kernel()
{
    __shared__ float sp[RT][RT + 1];

    const int tx = threadIdx.x % RT;
    const int ty = threadIdx.x / RT;
    const int e0 = blockIdx.x * RT;
    const int i0 = blockIdx.y * RT;
    const float scale = 17.320508075688775f;

    // phase 1: part sums, read e-fast (coalesced), store transposed
    {
        int i = i0 + ty, e = e0 + tx;
        float v = 0.f;
        if (i < D && e < D) {
            #pragma unroll
            for (int c = 0; c < NCH; ++c)
                v += g_part[(c * D + i) * D + e];
        }
        sp[ty][tx] = v;
    }
    __syncthreads();

    // phase 2: dpart sums, read i-fast (coalesced), add transposed part, store
    {
        int e = e0 + ty, i = i0 + tx;
        if (e < D && i < D) {
            float ds = 0.f;
            #pragma unroll
            for (int z = 0; z < DKZ; ++z)
                ds += g_dpart[z * D * D + e * D + i];
            g_diag[e * D + i] = fmaf(scale, sp[tx][ty], ds);
        }
    }
}

// ---------------------------------------------------------------------------
// Kernel 3: FC1 partials. grid (10,10,5): kz -> K window of 60.
//   g_hpart[kz][e][j] = sum_{k in window} diag[e][k] * w1[j][k]
// Single-plane diag staging. k-major smem tiles (pad 36, 16B-aligned).
// Thread tile 4e x 2j: 1 LDS.128 + 1 LDS.64 + 8 FMA per k.
// ---------------------------------------------------------------------------
__global__ __launch_bounds__(128) void fc1_kernel(
    const float* __restrict__ w1)
{
    __shared__ float sat[KT1][36];      // [k][e_local]
    __shared__ float sbt[KT1][36];      // [k][j_local]

    const int tx  = threadIdx.x;        // 0..15 -> j = j0 + 2*tx + {0,1}
    const int ty  = threadIdx.y;        // 0..7  -> e = e0 + 4*ty + {0..3}
    const int lin = ty * 16 + tx;
    const int j0  = blockIdx.x * 32;
    const int e0  = blockIdx.y * 32;
    const int kb  = blockIdx.z * KT1;

    float acc0[4] = {0.f, 0.f, 0.f, 0.f};
    float acc1[4] = {0.f, 0.f, 0.f, 0.f};

    // stage: 32 rows x 15 float4 per operand, written transposed
    for (int idx = lin; idx < 32 * 15; idx += 128) {
        int row = idx / 15;                 // e_local / j_local
        int kk  = (idx % 15) * 4;
        int k   = kb + kk;                  // max 240+56+3 = 299 < 300
        float4 va = make_float4(0.f, 0.f, 0.f, 0.f);
        float4 vb = va;
        if (e0 + row < D)
            va = *reinterpret_cast<const float4*>(g_diag + (e0 + row) * D + k);
        if (j0 + row < D)
            vb = *reinterpret_cast<const float4*>(w1 + (j0 + row) * D + k);
        sat[kk][row] = va.x; sat[kk + 1][row] = va.y;
        sat[kk + 2][row] = va.z; sat[kk + 3][row] = va.w;
        sbt[kk][row] = vb.x; sbt[kk + 1][row] = vb.y;
        sbt[kk + 2][row] = vb.z; sbt[kk + 3][row] = vb.w;
    }
    __syncthreads();

    #pragma unroll 6
    for (int k = 0; k < KT1; ++k) {
        float4 a = *reinterpret_cast<const float4*>(&sat[k][4 * ty]);
        float2 b = *reinterpret_cast<const float2*>(&sbt[k][2 * tx]);
        acc0[0] = fmaf(b.x, a.x, acc0[0]);
        acc0[1] = fmaf(b.x, a.y, acc0[1]);
        acc0[2] = fmaf(b.x, a.z, acc0[2]);
        acc0[3] = fmaf(b.x, a.w, acc0[3]);
        acc1[0] = fmaf(b.y, a.x, acc1[0]);
        acc1[1] = fmaf(b.y, a.y, acc1[1]);
        acc1[2] = fmaf(b.y, a.z, acc1[2]);
        acc1[3] = fmaf(b.y, a.w, acc1[3]);
    }

    const int kz = blockIdx.z;
    const int jp = j0 + 2 * tx;             // even pair
    if (jp < D) {
        #pragma unroll
        for (int u = 0; u < 4; ++u) {
            int e = e0 + 4 * ty + u;
            if (e < D) {
                float2 v = make_float2(acc0[u], acc1[u]);
                *reinterpret_cast<float2*>(g_hpart + kz * D * D + e * D + jp) = v;
            }
        }
    }
}

// ---------------------------------------------------------------------------
// Kernel 4: FC2 + softmax. One block per e-row. Folds hpart sum + bias + relu.
// ---------------------------------------------------------------------------
__global__ __launch_bounds__(128) void fc2_kernel(
    const float* __restrict__ b1,
    const float* __restrict__ w2,
    const float* __restrict__ b2,
    float*       __restrict__ out)
{
    const int e   = blockIdx.x;
    const int tid = threadIdx.x;

    float p[OUTC] = {0.f, 0.f, 0.f, 0.f};
    for (int j = tid; j < D; j += 128) {
        float hv = b1[j];
        #pragma unroll
        for (int z = 0; z < HKZ; ++z)
            hv += g_hpart[z * D * D + e * D + j];
        hv = fmaxf(hv, 0.f);
        #pragma unroll
        for (int o = 0; o < OUTC; ++o)
            p[o] = fmaf(hv, w2[o * D + j], p[o]);
    }

    #pragma unroll
    for (int off = 16; off > 0; off >>= 1) {
        #pragma unroll
        for (int o = 0; o < OUTC; ++o)
            p[o] += __shfl_xor_sync(0xFFFFFFFFu, p[o], off);
    }

    __shared__ float red[4][OUTC];
    const int wid = tid >> 5, lid = tid & 31;
    if (lid == 0) {
        #pragma unroll
        for (int o = 0; o < OUTC; ++o) red[wid][o] = p[o];
    }
    __syncthreads();

    if (tid == 0) {
        float logits[OUTC];
        #pragma unroll
        for (int o = 0; o < OUTC; ++o)
            logits[o] = red[0][o] + red[1][o] + red[2][o] + red[3][o] + b2[o];
        float m = fmaxf(fmaxf(logits[0], logits[1]), fmaxf(logits[2], logits[3]));
        float es[OUTC], ssum = 0.f;
        #pragma unroll
        for (int o = 0; o < OUTC; ++o) { es[o] = expf(logits[o] - m); ssum += es[o]; }
        float inv = 1.f / ssum;
        #pragma unroll
        for (int o = 0; o < OUTC; ++o) out[e * OUTC + o] = es[o] * inv;
    }
}

// ---------------------------------------------------------------------------
// Launch. Inputs: x1, x2 (i32 [512*512]); emb1, emb2 (f32 [32000*300]);
// w1 (f32 [300*300]); b1 (f32 [300]); w2 (f32 [4*300]); b2 (f32 [4]).
// Output: f32 [300*4].
// ---------------------------------------------------------------------------
extern "C" void kernel_launch(void* const* d_in, const int* in_sizes, int n_in,
                              void* d_out, int out_size) {
    const int*   x1   = (const int*)  d_in[0];
    const int*   x2   = (const int*)  d_in[1];
    const float* emb1 = (const float*)d_in[2];
    const float* emb2 = (const float*)d_in[3];
    const float* w1   = (const float*)d_in[4];
    const float* b1   = (const float*)d_in[5];
    const float* w2   = (const float*)d_in[6];
    const float* b2   = (const float*)d_in[7];
    float* out = (float*)d_out;

    pe_kernel<<<(LSEQ * D + 255) / 256, 256>>>();
    dim3 g1(NCH, D);
    term1_kernel<<<g1, 320>>>(x1, x2, emb1, emb2);
    combine_kernel<<<dim3(10, 10, DKZ), dim3(16, 8)>>>();
    reduce_kernel<<<dim3((D + RT - 1) / RT, (D + RT - 1) / RT), 256>>>();
    fc1_kernel<<<dim3(10, 10, HKZ), dim3(16, 8)>>>(w1);
    fc2_kernel<<<D, 128>>>(b1, w2, b2, out);
}

// round 10
// speedup vs baseline: 1.0564x; 1.0564x over previous
#include <cuda_runtime.h>
#include <math.h>

// D_MODEL=300, L=512, B=512, OUT=4.
// diag[e,i] = fmap[i,i,e] = sum_l e2[i,l,i] * e1[i,l,e], i in [0,300)
// Split:  diag[e,i] = scale * sum_l s[i,l]*emb1[x1[i,l]][e]      (term1, gather)
//                   +          sum_l s[i,l]*pe[l][e]             (term2, dense GEMM)
// with    s[i,l] = emb2[x2[i,l]][i]*scale + pe[l][i]

#define D     300
#define LSEQ  512
#define OUTC  4
#define NCH   4     // term1 l-split
#define CHUNK 128   // LSEQ / NCH
#define DKZ   4     // combine K-split (128 per block)
#define HKZ   5     // fc1 K-split
#define KT1   60    // fc1 K per block (5*60=300)

__device__ float g_pe[LSEQ * D];          // [l][d]
__device__ float g_s[D * LSEQ];           // [i][l]
__device__ float g_part[NCH * D * D];     // [chunk][i][e]  (term1 partials)
__device__ float g_dpart[DKZ * D * D];    // diag partials [kz][e][i]
                                          // (kz==0 plane includes term1)
__device__ float g_hpart[HKZ * D * D];    // fc1 partials  [kz][e][j]

// ---------------------------------------------------------------------------
// Kernel 0: positional encoding, float32 (matches jnp float32 path).
// ---------------------------------------------------------------------------
__global__ void pe_kernel() {
    int idx = blockIdx.x * blockDim.x + threadIdx.x;
    if (idx >= LSEQ * D) return;
    int l = idx / D;
    int d = idx % D;
    int k = d >> 1;
    const float coef = -9.210340371976184f / (float)D;   // -ln(10000)/300
    float divv = expf((float)(2 * k) * coef);
    float ang  = (float)l * divv;
    g_pe[idx] = (d & 1) ? cosf(ang) : sinf(ang);
}

// ---------------------------------------------------------------------------
// Kernel 1: term1 partials. One block per (i, l-chunk of 128). grid (4,300).
// ---------------------------------------------------------------------------
__global__ __launch_bounds__(320) void term1_kernel(
    const int*   __restrict__ x1,
    const int*   __restrict__ x2,
    const float* __restrict__ emb1,
    const float* __restrict__ emb2)
{
    const int chunk = blockIdx.x;          // 0..3
    const int i     = blockIdx.y;          // 0..299
    const int tid   = threadIdx.x;
    const float scale = 17.320508075688775f;  // sqrt(300)

    __shared__ float s_sh[CHUNK];
    __shared__ int   r1_sh[CHUNK];

    if (tid < CHUNK) {
        int l  = chunk * CHUNK + tid;
        int t2 = x2[i * LSEQ + l];
        float sv = fmaf(emb2[t2 * D + i], scale, g_pe[l * D + i]);
        s_sh[tid] = sv;
        g_s[i * LSEQ + l] = sv;
        r1_sh[tid] = x1[i * LSEQ + l] * D;
    }
    __syncthreads();

    if (tid < D) {
        const int e = tid;
        float acc[8];
        #pragma unroll
        for (int u = 0; u < 8; ++u) acc[u] = 0.f;
        #pragma unroll 2
        for (int l = 0; l < CHUNK; l += 8) {
            #pragma unroll
            for (int u = 0; u < 8; ++u)
                acc[u] = fmaf(s_sh[l + u], emb1[r1_sh[l + u] + e], acc[u]);
        }
        float r = ((acc[0] + acc[1]) + (acc[2] + acc[3]))
                + ((acc[4] + acc[5]) + (acc[6] + acc[7]));
        g_part[(chunk * D + i) * D + e] = r;
    }
}

// ---------------------------------------------------------------------------
// Kernel 2: term2 GEMM partials; kz==0 blocks also fold the term1 partials
// (smem-transposed, coalesced).
//   g_dpart[kz][e][i] = sum_{l in 128-window kz} s[i,l]*pe[l][e]
//                       (+ scale*sum_c part[c][i][e] when kz==0)
// grid (10,10,4), 128 threads (16,8). Thread tile 4e x 2i (tx -> i:
// coalesced float2 stores). k-major smem tiles for vector LDS.
// ---------------------------------------------------------------------------
__global__ __launch_bounds__(128) void combine_kernel()
{
    __shared__ float sh_st[128][34];   // [k][i_local]; reused for part fold
    __shared__ float sh_pe[128][36];   // [k][e_local], 16B-aligned rows

    const int tx  = threadIdx.x;       // 0..15 -> i = i0 + 2*tx + {0,1}
    const int ty  = threadIdx.y;       // 0..7  -> e = e0 + 4*ty + {0..3}
    const int lin = ty * 16 + tx;
    const int e0  = blockIdx.x * 32;
    const int i0  = blockIdx.y * 32;
    const int kz  = blockIdx.z;        // 0..3
    const int kb  = kz * 128;

    const float scale = 17.320508075688775f;

    float acc0[4] = {0.f, 0.f, 0.f, 0.f};   // i = i0+2tx
    float acc1[4] = {0.f, 0.f, 0.f, 0.f};   // i = i0+2tx+1

    // stage s tile transposed: 32 i-rows x 128 k (float4 reads, scalar stores)
    #pragma unroll
    for (int t = 0; t < 8; ++t) {
        int idx = lin + t * 128;           // 0..1023
        int row = idx >> 5;                // 0..31 (i_local)
        int kk  = (idx & 31) * 4;          // 0..124
        float4 v = make_float4(0.f, 0.f, 0.f, 0.f);
        int ii = i0 + row;
        if (ii < D)
            v = *reinterpret_cast<const float4*>(g_s + ii * LSEQ + kb + kk);
        sh_st[kk][row] = v.x; sh_st[kk + 1][row] = v.y;
        sh_st[kk + 2][row] = v.z; sh_st[kk + 3][row] = v.w;
    }
    // stage pe tile (naturally k-major): 128 k-rows x 32 e (float4)
    #pragma unroll
    for (int t = 0; t < 8; ++t) {
        int idx = lin + t * 128;           // 0..1023
        int row = idx >> 3;                // 0..127 (k_local)
        int cc  = (idx & 7) * 4;           // 0..28
        int e   = e0 + cc;
        float4 v = make_float4(0.f, 0.f, 0.f, 0.f);
        if (e <= D - 4)
            v = *reinterpret_cast<const float4*>(g_pe + (kb + row) * D + e);
        *reinterpret_cast<float4*>(&sh_pe[row][cc]) = v;
    }
    __syncthreads();

    #pragma unroll 4
    for (int k = 0; k < 128; ++k) {
        float2 sv = *reinterpret_cast<const float2*>(&sh_st[k][2 * tx]);
        float4 pv = *reinterpret_cast<const float4*>(&sh_pe[k][4 * ty]);
        acc0[0] = fmaf(sv.x, pv.x, acc0[0]);
        acc0[1] = fmaf(sv.x, pv.y, acc0[1]);
        acc0[2] = fmaf(sv.x, pv.z, acc0[2]);
        acc0[3] = fmaf(sv.x, pv.w, acc0[3]);
        acc1[0] = fmaf(sv.y, pv.x, acc1[0]);
        acc1[1] = fmaf(sv.y, pv.y, acc1[1]);
        acc1[2] = fmaf(sv.y, pv.z, acc1[2]);
        acc1[3] = fmaf(sv.y, pv.w, acc1[3]);
    }

    // kz==0: fold term1 partials via smem transpose.
    // Read part[c][i][e] e-fast (coalesced), store sp[i_local][e_local].
    if (kz == 0) {
        __syncthreads();
        #pragma unroll
        for (int t = 0; t < 8; ++t) {
            int idx = lin + t * 128;       // 0..1023
            int row = idx >> 5;            // i_local
            int col = idx & 31;            // e_local
            int i = i0 + row, e = e0 + col;
            float v = 0.f;
            if (i < D && e < D) {
                #pragma unroll
                for (int c = 0; c < NCH; ++c)
                    v += g_part[(c * D + i) * D + e];
            }
            sh_st[row][col] = v;           // reuse sh_st as [32][34] view
        }
        __syncthreads();
        #pragma unroll
        for (int u = 0; u < 4; ++u) {
            acc0[u] = fmaf(scale, sh_st[2 * tx][4 * ty + u], acc0[u]);
            acc1[u] = fmaf(scale, sh_st[2 * tx + 1][4 * ty + u], acc1[u]);
        }
    }

    const int ip = i0 + 2 * tx;             // even pair (ip, ip+1)
    if (ip < D) {                            // D even -> pair fully valid
        #pragma unroll
        for (int u = 0; u < 4; ++u) {
            int e = e0 + 4 * ty + u;
            if (e < D) {
                float2 v = make_float2(acc0[u], acc1[u]);
                *reinterpret_cast<float2*>(g_dpart + kz * D * D + e * D + ip) = v;
            }
        }
    }
}

// ---------------------------------------------------------------------------
// Kernel 3: FC1 partials. grid (10,10,5): kz -> K window of 60.
//   g_hpart[kz][e][j] = sum_{k in window} diag[e][k] * w1[j][k]
// diag = sum of 4 dpart planes (summed at staging; coalesced float4 reads).
// k-major smem tiles (pad 36, 16B-aligned). Thread tile 4e x 2j:
// 1 LDS.128 + 1 LDS.64 + 8 FMA per k.
// ---------------------------------------------------------------------------
__global__ __launch_bounds__(128) void fc1_kernel(
    const float* __restrict__ w1)
{
    __shared__ float sat[KT1][36];      // [k][e_local]
    __shared__ float sbt[KT1][36];      // [k][j_local]

    const int tx  = threadIdx.x;        // 0..15 -> j = j0 + 2*tx + {0,1}
    const int ty  = threadIdx.y;        // 0..7  -> e = e0 + 4*ty + {0..3}
    const int lin = ty * 16 + tx;
    const int j0  = blockIdx.x * 32;
    const int e0  = blockIdx.y * 32;
    const int kb  = blockIdx.z * KT1;

    float acc0[4] = {0.f, 0.f, 0.f, 0.f};
    float acc1[4] = {0.f, 0.f, 0.f, 0.f};

    // stage: 32 rows x 15 float4 per operand, written transposed
    for (int idx = lin; idx < 32 * 15; idx += 128) {
        int row = idx / 15;                 // e_local / j_local
        int kk  = (idx % 15) * 4;
        int k   = kb + kk;                  // max 240+56+3 = 299 < 300
        float4 va = make_float4(0.f, 0.f, 0.f, 0.f);
        float4 vb = va;
        if (e0 + row < D) {
            #pragma unroll
            for (int z = 0; z < DKZ; ++z) {
                float4 v = *reinterpret_cast<const float4*>(
                    g_dpart + z * D * D + (e0 + row) * D + k);
                va.x += v.x; va.y += v.y; va.z += v.z; va.w += v.w;
            }
        }
        if (j0 + row < D)
            vb = *reinterpret_cast<const float4*>(w1 + (j0 + row) * D + k);
        sat[kk][row] = va.x; sat[kk + 1][row] = va.y;
        sat[kk + 2][row] = va.z; sat[kk + 3][row] = va.w;
        sbt[kk][row] = vb.x; sbt[kk + 1][row] = vb.y;
        sbt[kk + 2][row] = vb.z; sbt[kk + 3][row] = vb.w;
    }
    __syncthreads();

    #pragma unroll 6
    for (int k = 0; k < KT1; ++k) {
        float4 a = *reinterpret_cast<const float4*>(&sat[k][4 * ty]);
        float2 b = *reinterpret_cast<const float2*>(&sbt[k][2 * tx]);
        acc0[0] = fmaf(b.x, a.x, acc0[0]);
        acc0[1] = fmaf(b.x, a.y, acc0[1]);
        acc0[2] = fmaf(b.x, a.z, acc0[2]);
        acc0[3] = fmaf(b.x, a.w, acc0[3]);
        acc1[0] = fmaf(b.y, a.x, acc1[0]);
        acc1[1] = fmaf(b.y, a.y, acc1[1]);
        acc1[2] = fmaf(b.y, a.z, acc1[2]);
        acc1[3] = fmaf(b.y, a.w, acc1[3]);
    }

    const int kz = blockIdx.z;
    const int jp = j0 + 2 * tx;             // even pair
    if (jp < D) {
        #pragma unroll
        for (int u = 0; u < 4; ++u) {
            int e = e0 + 4 * ty + u;
            if (e < D) {
                float2 v = make_float2(acc0[u], acc1[u]);
                *reinterpret_cast<float2*>(g_hpart + kz * D * D + e * D + jp) = v;
            }
        }
    }
}

// ---------------------------------------------------------------------------
// Kernel 4: FC2 + softmax. One block per e-row. Folds hpart sum + bias + relu.
// ---------------------------------------------------------------------------
__global__ __launch_bounds__(128) void fc2_kernel(
    const float* __restrict__ b1,
    const float* __restrict__ w2,
    const float* __restrict__ b2,
    float*       __restrict__ out)
{
    const int e   = blockIdx.x;
    const int tid = threadIdx.x;

    float p[OUTC] = {0.f, 0.f, 0.f, 0.f};
    for (int j = tid; j < D; j += 128) {
        float hv = b1[j];
        #pragma unroll
        for (int z = 0; z < HKZ; ++z)
            hv += g_hpart[z * D * D + e * D + j];
        hv = fmaxf(hv, 0.f);
        #pragma unroll
        for (int o = 0; o < OUTC; ++o)
            p[o] = fmaf(hv, w2[o * D + j], p[o]);
    }

    #pragma unroll
    for (int off = 16; off > 0; off >>= 1) {
        #pragma unroll
        for (int o = 0; o < OUTC; ++o)
            p[o] += __shfl_xor_sync(0xFFFFFFFFu, p[o], off);
    }

    __shared__ float red[4][OUTC];
    const int wid = tid >> 5, lid = tid & 31;
    if (lid == 0) {
        #pragma unroll
        for (int o = 0; o < OUTC; ++o) red[wid][o] = p[o];
    }
    __syncthreads();

    if (tid == 0) {
        float logits[OUTC];
        #pragma unroll
        for (int o = 0; o < OUTC; ++o)
            logits[o] = red[0][o] + red[1][o] + red[2][o] + red[3][o] + b2[o];
        float m = fmaxf(fmaxf(logits[0], logits[1]), fmaxf(logits[2], logits[3]));
        float es[OUTC], ssum = 0.f;
        #pragma unroll
        for (int o = 0; o < OUTC; ++o) { es[o] = expf(logits[o] - m); ssum += es[o]; }
        float inv = 1.f / ssum;
        #pragma unroll
        for (int o = 0; o < OUTC; ++o) out[e * OUTC + o] = es[o] * inv;
    }
}

// ---------------------------------------------------------------------------
// Launch. Inputs: x1, x2 (i32 [512*512]); emb1, emb2 (f32 [32000*300]);
// w1 (f32 [300*300]); b1 (f32 [300]); w2 (f32 [4*300]); b2 (f32 [4]).
// Output: f32 [300*4].
// ---------------------------------------------------------------------------
extern "C" void kernel_launch(void* const* d_in, const int* in_sizes, int n_in,
                              void* d_out, int out_size) {
    const int*   x1   = (const int*)  d_in[0];
    const int*   x2   = (const int*)  d_in[1];
    const float* emb1 = (const float*)d_in[2];
    const float* emb2 = (const float*)d_in[3];
    const float* w1   = (const float*)d_in[4];
    const float* b1   = (const float*)d_in[5];
    const float* w2   = (const float*)d_in[6];
    const float* b2   = (const float*)d_in[7];
    float* out = (float*)d_out;

    pe_kernel<<<(LSEQ * D + 255) / 256, 256>>>();
    dim3 g1(NCH, D);
    term1_kernel<<<g1, 320>>>(x1, x2, emb1, emb2);
    combine_kernel<<<dim3(10, 10, DKZ), dim3(16, 8)>>>();
    fc1_kernel<<<dim3(10, 10, HKZ), dim3(16, 8)>>>(w1);
    fc2_kernel<<<D, 128>>>(b1, w2, b2, out);
}